// round 17
// baseline (speedup 1.0000x reference)
#include <cuda_runtime.h>
#include <cuda_fp16.h>
#include <cstdint>

// Problem dims
#define BB 32     // batch
#define TE 800    // encoder timesteps
#define TD 400    // decoder timesteps
#define ED 256    // encoder feature dim
#define AD 128    // attention dim
#define GD 256    // GRU dim
#define ID 80     // input dim

// ---------------------------------------------------------------------------
// Scratch (__device__ globals)
// ---------------------------------------------------------------------------
__device__ __half g_eph[(size_t)BB * TE * AD];    // enc_proj (b,t,a) fp16
__device__ __half g_encTh[(size_t)BB * ED * TE];  // enc transposed (b,e,t) fp16
__device__ float  g_gix[(size_t)BB * TD * 768];   // x-part GRU preacts + folded biases
__device__ __half g_WGh[256 * 1536];              // per-i packed GRU weights fp16
__device__ __half g_WOh[80 * 512];                // W_out permuted to [ctx|h], fp16
__device__ __half g_Wdh[128 * 256];               // W_dec fp16

// ---------------------------------------------------------------------------
// Helpers
// ---------------------------------------------------------------------------
__device__ __forceinline__ float dot4(float4 a, float4 b) {
    return fmaf(a.x, b.x, fmaf(a.y, b.y, fmaf(a.z, b.z, a.w * b.w)));
}
__device__ __forceinline__ float4 h4tof4(uint2 u) {
    __half2 a = *reinterpret_cast<__half2*>(&u.x);
    __half2 b = *reinterpret_cast<__half2*>(&u.y);
    float2 fa = __half22float2(a), fb = __half22float2(b);
    return make_float4(fa.x, fa.y, fb.x, fb.y);
}
__device__ __forceinline__ void h8tof8(uint4 u, float4& A, float4& B) {
    A = h4tof4(make_uint2(u.x, u.y));
    B = h4tof4(make_uint2(u.z, u.w));
}
__device__ __forceinline__ float wsum(float v) {
    v += __shfl_down_sync(0xffffffffu, v, 16);
    v += __shfl_down_sync(0xffffffffu, v, 8);
    v += __shfl_down_sync(0xffffffffu, v, 4);
    v += __shfl_down_sync(0xffffffffu, v, 2);
    v += __shfl_down_sync(0xffffffffu, v, 1);
    return v;  // lane 0 valid
}
__device__ __forceinline__ float wallmax(float v) {
    #pragma unroll
    for (int s = 16; s > 0; s >>= 1) v = fmaxf(v, __shfl_xor_sync(0xffffffffu, v, s));
    return v;
}
__device__ __forceinline__ float wallsum(float v) {
    #pragma unroll
    for (int s = 16; s > 0; s >>= 1) v += __shfl_xor_sync(0xffffffffu, v, s);
    return v;
}
__device__ __forceinline__ float ftanh(float x) {
    float y;
    asm("tanh.approx.f32 %0, %1;" : "=f"(y) : "f"(x));
    return y;
}
__device__ __forceinline__ uint32_t smem_u32(const void* p) {
    uint32_t a;
    asm("{ .reg .u64 t; cvta.to.shared.u64 t, %1; cvt.u32.u64 %0, t; }" : "=r"(a) : "l"(p));
    return a;
}
__device__ __forceinline__ void st_cluster(uint32_t laddr, uint32_t rank, float v) {
    uint32_t ra;
    asm volatile("mapa.shared::cluster.u32 %0, %1, %2;" : "=r"(ra) : "r"(laddr), "r"(rank));
    asm volatile("st.shared::cluster.f32 [%0], %1;" :: "r"(ra), "f"(v) : "memory");
}
__device__ __forceinline__ void bcast4(const void* p, float v) {
    uint32_t la = smem_u32(p);
    #pragma unroll
    for (uint32_t r = 0; r < 4; ++r) st_cluster(la, r, v);
}
__device__ __forceinline__ void red_add_rank(uint32_t laddr, uint32_t rank, float v) {
    uint32_t ra;
    asm volatile("mapa.shared::cluster.u32 %0, %1, %2;" : "=r"(ra) : "r"(laddr), "r"(rank));
    asm volatile("red.relaxed.cluster.shared::cluster.add.f32 [%0], %1;"
                 :: "r"(ra), "f"(v) : "memory");
}
__device__ __forceinline__ void radd4(const void* p, float v) {
    uint32_t la = smem_u32(p);
    #pragma unroll
    for (uint32_t r = 0; r < 4; ++r) red_add_rank(la, r, v);
}
__device__ __forceinline__ void cluster_sync() {
    asm volatile("barrier.cluster.arrive.aligned;" ::: "memory");
    asm volatile("barrier.cluster.wait.aligned;" ::: "memory");
}

// ---------------------------------------------------------------------------
// prep_repack
// ---------------------------------------------------------------------------
__global__ void prep_repack(const float* __restrict__ W_ih,
                            const float* __restrict__ W_hh,
                            const float* __restrict__ W_out,
                            const float* __restrict__ W_dec) {
    int stride = gridDim.x * blockDim.x;
    int g = blockIdx.x * blockDim.x + threadIdx.x;
    for (int idx = g; idx < 256 * 1536; idx += stride) {
        int i = idx / 1536, c = idx % 1536;
        int seg = c >> 8, cc = c & 255;
        float v;
        switch (seg) {
            case 0:  v = W_ih[(size_t)i * 336 + 80 + cc]; break;
            case 1:  v = W_hh[(size_t)i * 256 + cc]; break;
            case 2:  v = W_ih[(size_t)(256 + i) * 336 + 80 + cc]; break;
            case 3:  v = W_hh[(size_t)(256 + i) * 256 + cc]; break;
            case 4:  v = W_ih[(size_t)(512 + i) * 336 + 80 + cc]; break;
            default: v = W_hh[(size_t)(512 + i) * 256 + cc]; break;
        }
        g_WGh[idx] = __float2half(v);
    }
    for (int idx = g; idx < 80 * 512; idx += stride) {
        int r = idx >> 9, c = idx & 511;
        float v = (c < 256) ? W_out[(size_t)r * 512 + 256 + c]
                            : W_out[(size_t)r * 512 + (c - 256)];
        g_WOh[idx] = __float2half(v);
    }
    for (int idx = g; idx < 128 * 256; idx += stride)
        g_Wdh[idx] = __float2half(W_dec[idx]);
}

// ---------------------------------------------------------------------------
// prep_encproj
// ---------------------------------------------------------------------------
__global__ void __launch_bounds__(256) prep_encproj(const float* __restrict__ enc,
                                                    const float* __restrict__ W_enc) {
    __shared__ float x[16 * ED];
    int m0 = blockIdx.x * 16;
    int tid = threadIdx.x;
    const float4* src = (const float4*)(enc + (size_t)m0 * ED);
    float4* xd = (float4*)x;
    #pragma unroll
    for (int q = 0; q < 4; ++q) xd[tid + 256 * q] = src[tid + 256 * q];
    __syncthreads();

    int a = tid & 127, half = tid >> 7;
    const float4* wr = (const float4*)(W_enc + (size_t)a * ED);
    float acc[8] = {0.f, 0.f, 0.f, 0.f, 0.f, 0.f, 0.f, 0.f};
    for (int k4 = 0; k4 < 64; ++k4) {
        float4 wv = wr[k4];
        #pragma unroll
        for (int i = 0; i < 8; ++i) {
            float4 xv = xd[(8 * half + i) * 64 + k4];
            acc[i] += dot4(wv, xv);
        }
    }
    #pragma unroll
    for (int i = 0; i < 8; ++i)
        g_eph[(size_t)(m0 + 8 * half + i) * AD + a] = __float2half(acc[i]);
}

// ---------------------------------------------------------------------------
// prep_transpose: enc (b,t,e) fp32 -> g_encTh (b,e,t) fp16
// ---------------------------------------------------------------------------
__global__ void prep_transpose(const float* __restrict__ enc) {
    __shared__ float tile[32][33];
    int b = blockIdx.z;
    int t0 = blockIdx.x * 32, e0 = blockIdx.y * 32;
    int tx = threadIdx.x, ty = threadIdx.y;
    #pragma unroll
    for (int k = 0; k < 4; ++k)
        tile[ty + 8 * k][tx] = enc[((size_t)b * TE + t0 + ty + 8 * k) * ED + e0 + tx];
    __syncthreads();
    #pragma unroll
    for (int k = 0; k < 4; ++k)
        g_encTh[((size_t)b * ED + e0 + ty + 8 * k) * TE + t0 + tx] =
            __float2half(tile[tx][ty + 8 * k]);
}

// ---------------------------------------------------------------------------
// prep_gix
// ---------------------------------------------------------------------------
__global__ void __launch_bounds__(256) prep_gix(const float* __restrict__ gt,
                                                const float* __restrict__ W_ih,
                                                const float* __restrict__ b_ih,
                                                const float* __restrict__ b_hh) {
    __shared__ float x[8 * ID];
    int m0 = blockIdx.x * 8;
    int tid = threadIdx.x;
    if (tid < 160) ((float4*)x)[tid] = ((const float4*)(gt + (size_t)m0 * ID))[tid];
    __syncthreads();

    #pragma unroll
    for (int j = 0; j < 3; ++j) {
        int r = 256 * j + tid;
        const float* wr = W_ih + (size_t)r * 336;
        float acc[8] = {0.f, 0.f, 0.f, 0.f, 0.f, 0.f, 0.f, 0.f};
        #pragma unroll 4
        for (int k4 = 0; k4 < 20; ++k4) {
            float4 wv = *(const float4*)(wr + 4 * k4);
            #pragma unroll
            for (int i = 0; i < 8; ++i) {
                float4 xv = ((float4*)x)[i * 20 + k4];
                acc[i] += dot4(wv, xv);
            }
        }
        float bias = (r < 512) ? (b_ih[r] + b_hh[r]) : b_ih[r];
        #pragma unroll
        for (int i = 0; i < 8; ++i)
            g_gix[(size_t)(m0 + i) * 768 + r] = acc[i] + bias;
    }
}

// ---------------------------------------------------------------------------
// Decoder workspace (dynamic SMEM after the weight slice)
// ---------------------------------------------------------------------------
struct Work {
    float buf[2][512];     // ping-pong [ctx_raw(256); h(256)]; ctx atomic-reduced
    float attn[2][200];    // own exp slice, double buffered (local only)
    float dp[128];         // full dec_proj, computed redundantly per CTA
    float cpart[256];      // this CTA's ctx partial (own 200-t slice)
    float o_ctx[2][80];    // ctx-part logits, atomic-reduced into rank 0
    float o_h[2][80];      // rank0-local h-part logits + b_out
    float pre[4][64];      // gate partials
    float red[32];
    float S[2];            // exp-score sums, atomic-reduced (replicated)
    float pad[2];
};
#define WG_SLICE_BYTES (64 * 1536 * 2)
#define DSMEM_BYTES (WG_SLICE_BYTES + (int)sizeof(Work))

// ---------------------------------------------------------------------------
// Decoder: 4-CTA cluster per batch, 1024 thr/CTA, TWO cluster syncs per step.
// rank rk owns: gates [64rk,+64) and the t-slice [200rk,+200) of scores/ctx.
// ---------------------------------------------------------------------------
__global__ void __launch_bounds__(1024, 1) __cluster_dims__(4, 1, 1)
decoder_kernel(const float* __restrict__ b_attn,
               const float* __restrict__ v_attn,
               const float* __restrict__ b_hh,
               const float* __restrict__ b_out,
               float* __restrict__ out) {
    extern __shared__ char dsm[];
    __half* sWG = (__half*)dsm;                       // [64][1536]
    Work* Wk = (Work*)(dsm + WG_SLICE_BYTES);

    const int b = blockIdx.x >> 2;
    uint32_t rk;
    asm("mov.u32 %0, %%cluster_ctarank;" : "=r"(rk));
    const int tid = threadIdx.x, w = tid >> 5, l = tid & 31;

    // one-time: this CTA's GRU weight slice -> SMEM (12288 uint4)
    {
        const uint4* src = (const uint4*)(g_WGh + (size_t)(64 * rk) * 1536);
        uint4* dst = (uint4*)sWG;
        #pragma unroll
        for (int i = 0; i < 12; ++i) dst[tid + 1024 * i] = src[tid + 1024 * i];
    }
    if (tid < 512) Wk->buf[0][tid] = 0.f;
    if (tid == 0) Wk->S[1] = 1.0f;     // t=0 reads S[(t-1)&1] = S[1]; ctx=0 so inv value moot

    const float4 vf = *(const float4*)(v_attn + 4 * l);
    const __half* eph_b = g_eph + (size_t)b * TE * AD;
    const __half* eTh_b = g_encTh + (size_t)b * ED * TE;
    const size_t attn_base = (size_t)BB * TD * ID;
    __syncthreads();

    int p = 0;
    for (int t = 0; t < TD; ++t) {
        const float* gix = g_gix + ((size_t)b * TD + t) * 768;
        const float inv = 1.f / Wk->S[(t - 1) & 1];

        // ---- phase PRE-A: GRU dots on [ctx_raw*inv ; h] -----------------
        float4 ia0 = *(const float4*)(Wk->buf[p] + 8 * l);
        float4 ia1 = *(const float4*)(Wk->buf[p] + 8 * l + 4);
        float4 ib0 = *(const float4*)(Wk->buf[p] + 256 + 8 * l);
        float4 ib1 = *(const float4*)(Wk->buf[p] + 256 + 8 * l + 4);
        ia0.x *= inv; ia0.y *= inv; ia0.z *= inv; ia0.w *= inv;
        ia1.x *= inv; ia1.y *= inv; ia1.z *= inv; ia1.w *= inv;

        #pragma unroll
        for (int ii = 0; ii < 2; ++ii) {
            int il = w * 2 + ii;
            int ig = 64 * (int)rk + il;
            const uint4* wr = (const uint4*)(sWG + (size_t)il * 1536);
            float4 A, B, C, D;
            uint4 u0 = wr[l], u1 = wr[32 + l];                // r gate
            h8tof8(u0, A, B); h8tof8(u1, C, D);
            float accR = dot4(A, ia0) + dot4(B, ia1) + dot4(C, ib0) + dot4(D, ib1);
            uint4 u2 = wr[64 + l], u3 = wr[96 + l];           // z gate
            h8tof8(u2, A, B); h8tof8(u3, C, D);
            float accZ = dot4(A, ia0) + dot4(B, ia1) + dot4(C, ib0) + dot4(D, ib1);
            uint4 u4 = wr[128 + l];                           // n gate, ctx part
            h8tof8(u4, A, B);
            float accB = dot4(A, ia0) + dot4(B, ia1);
            uint4 u5 = wr[160 + l];                           // n gate, h part
            h8tof8(u5, C, D);
            float accC = dot4(C, ib0) + dot4(D, ib1);
            accR = wsum(accR); accZ = wsum(accZ);
            accB = wsum(accB); accC = wsum(accC);
            if (l == 0) {
                Wk->pre[0][il] = accR + gix[ig];
                Wk->pre[1][il] = accZ + gix[256 + ig];
                Wk->pre[2][il] = accB + gix[512 + ig];
                Wk->pre[3][il] = accC;
            }
        }

        // zero next-step accumulators (remote adds only land post-sync-A)
        if (tid < 256) Wk->buf[p ^ 1][tid] = 0.f;       // ctx accumulator
        if (tid < 80) Wk->o_ctx[t & 1][tid] = 0.f;      // logit-ctx accumulator
        if (tid == 1023) Wk->S[t & 1] = 0.f;            // score-sum accumulator

        // deferred attn write for step t-1 (own 200 slice, local exp * inv)
        if (t > 0 && tid < 200)
            out[attn_base + ((size_t)b * TD + (t - 1)) * TE + 200 * (int)rk + tid] =
                Wk->attn[(t - 1) & 1][tid] * inv;

        __syncthreads();

        // gates -> h_new broadcast
        if (tid < 64) {
            int ig = 64 * (int)rk + tid;
            float r = 1.f / (1.f + __expf(-Wk->pre[0][tid]));
            float z = 1.f / (1.f + __expf(-Wk->pre[1][tid]));
            float hn = Wk->pre[3][tid] + b_hh[512 + ig];
            float n = tanhf(fmaf(r, hn, Wk->pre[2][tid]));
            float ho = Wk->buf[p][256 + ig];
            bcast4(&Wk->buf[p ^ 1][256 + ig], fmaf(z, ho - n, n));
        }
        // deferred log_softmax of step t-1 (rank0, warp 31; concurrent with gates)
        if (t > 0 && rk == 0 && w == 31) {
            const float* oc = Wk->o_ctx[(t - 1) & 1];
            const float* oh = Wk->o_h[(t - 1) & 1];
            float v0 = fmaf(oc[l], inv, oh[l]);
            float v1 = fmaf(oc[32 + l], inv, oh[32 + l]);
            float v2 = (l < 16) ? fmaf(oc[64 + l], inv, oh[64 + l]) : -1e30f;
            float mm = wallmax(fmaxf(fmaxf(v0, v1), v2));
            float se = __expf(v0 - mm) + __expf(v1 - mm) +
                       ((l < 16) ? __expf(v2 - mm) : 0.f);
            se = wallsum(se);
            float ls = mm + logf(se);
            float* pr = out + ((size_t)b * TD + (t - 1)) * ID;
            pr[l] = v0 - ls;
            pr[32 + l] = v1 - ls;
            if (l < 16) pr[64 + l] = v2 - ls;
        }
        cluster_sync();  // A: h_new visible everywhere

        // ---- dp: ALL 128 rows, redundantly (no broadcast, no sync) ------
        {
            float4 h0 = *(const float4*)(Wk->buf[p ^ 1] + 256 + 8 * l);
            float4 h1 = *(const float4*)(Wk->buf[p ^ 1] + 256 + 8 * l + 4);
            #pragma unroll
            for (int i = 0; i < 4; ++i) {
                int a = 4 * w + i;
                uint4 u = ((const uint4*)g_Wdh)[a * 32 + l];
                float4 A, B;
                h8tof8(u, A, B);
                float acc = dot4(A, h0) + dot4(B, h1);
                acc = wsum(acc);
                if (l == 0) Wk->dp[a] = acc + b_attn[a];
            }
        }
        __syncthreads();

        // ---- scores for OWN 200-t slice (local store, no broadcast) -----
        {
            float4 dp = *(const float4*)(Wk->dp + 4 * l);
            for (int tt = w; tt < 200; tt += 32) {
                int tg = 200 * (int)rk + tt;
                float4 ep = h4tof4(((const uint2*)(eph_b + (size_t)tg * AD))[l]);
                float s = vf.x * ftanh(ep.x + dp.x);
                s = fmaf(vf.y, ftanh(ep.y + dp.y), s);
                s = fmaf(vf.z, ftanh(ep.z + dp.z), s);
                s = fmaf(vf.w, ftanh(ep.w + dp.w), s);
                s = wsum(s);
                if (l == 0) Wk->attn[t & 1][tt] = __expf(s);
            }
        }
        __syncthreads();

        // ---- local score sum -> atomic add into all 4 ranks' S ----------
        {
            float sv = (tid < 200) ? Wk->attn[t & 1][tid] : 0.f;
            sv = wsum(sv);
            if (l == 0) Wk->red[w] = sv;
        }
        __syncthreads();
        if (tid == 0) {
            float s = 0.f;
            #pragma unroll
            for (int i = 0; i < 7; ++i) s += Wk->red[i];
            radd4(&Wk->S[t & 1], s);
        }

        // ---- ctx partials: all 256 e over OWN 200 t; atomic-reduce ------
        #pragma unroll
        for (int j = 0; j < 8; ++j) {
            int e = 8 * w + j;
            const uint4* er = (const uint4*)(eTh_b + (size_t)e * TE + 200 * (int)rk);
            float acc = 0.f;
            if (l < 25) {
                float4 A, B;
                h8tof8(er[l], A, B);
                float4 a0 = *(const float4*)(Wk->attn[t & 1] + 8 * l);
                float4 a1 = *(const float4*)(Wk->attn[t & 1] + 8 * l + 4);
                acc = dot4(A, a0) + dot4(B, a1);
            }
            acc = wsum(acc);
            if (l == 0) {
                Wk->cpart[e] = acc;
                radd4(&Wk->buf[p ^ 1][e], acc);
            }
        }
        __syncthreads();  // cpart complete

        // ---- logit partials: 80 rows x cpart(256); reduce into rank 0 ---
        if (w < 20) {
            float4 c0 = *(const float4*)(Wk->cpart + 8 * l);
            float4 c1 = *(const float4*)(Wk->cpart + 8 * l + 4);
            float4 h0 = *(const float4*)(Wk->buf[p ^ 1] + 256 + 8 * l);
            float4 h1 = *(const float4*)(Wk->buf[p ^ 1] + 256 + 8 * l + 4);
            #pragma unroll
            for (int i = 0; i < 4; ++i) {
                int o = 4 * w + i;
                uint4 u = ((const uint4*)g_WOh)[o * 64 + l];
                float4 A, B;
                h8tof8(u, A, B);
                float accC = dot4(A, c0) + dot4(B, c1);
                accC = wsum(accC);
                if (l == 0) red_add_rank(smem_u32(&Wk->o_ctx[t & 1][o]), 0, accC);
                if (rk == 0) {   // h-part + b_out, not inv-scaled, rank0-local
                    uint4 uh = ((const uint4*)g_WOh)[o * 64 + 32 + l];
                    float4 C, D;
                    h8tof8(uh, C, D);
                    float accH = dot4(C, h0) + dot4(D, h1);
                    accH = wsum(accH);
                    if (l == 0) Wk->o_h[t & 1][o] = accH + b_out[o];
                }
            }
        }
        cluster_sync();  // B: ctx/S/logit reductions visible; step boundary
        p ^= 1;
    }

    // final flush for step TD-1
    {
        const float inv = 1.f / Wk->S[(TD - 1) & 1];
        if (tid < 200)
            out[attn_base + ((size_t)b * TD + (TD - 1)) * TE + 200 * (int)rk + tid] =
                Wk->attn[(TD - 1) & 1][tid] * inv;
        if (rk == 0 && w == 0) {
            const float* oc = Wk->o_ctx[(TD - 1) & 1];
            const float* oh = Wk->o_h[(TD - 1) & 1];
            float v0 = fmaf(oc[l], inv, oh[l]);
            float v1 = fmaf(oc[32 + l], inv, oh[32 + l]);
            float v2 = (l < 16) ? fmaf(oc[64 + l], inv, oh[64 + l]) : -1e30f;
            float mm = wallmax(fmaxf(fmaxf(v0, v1), v2));
            float se = __expf(v0 - mm) + __expf(v1 - mm) +
                       ((l < 16) ? __expf(v2 - mm) : 0.f);
            se = wallsum(se);
            float ls = mm + logf(se);
            float* pr = out + ((size_t)b * TD + (TD - 1)) * ID;
            pr[l] = v0 - ls;
            pr[32 + l] = v1 - ls;
            if (l < 16) pr[64 + l] = v2 - ls;
        }
    }
}

// ---------------------------------------------------------------------------
// Launch
// ---------------------------------------------------------------------------
extern "C" void kernel_launch(void* const* d_in, const int* in_sizes, int n_in,
                              void* d_out, int out_size) {
    const float* enc    = (const float*)d_in[0];
    const float* gt     = (const float*)d_in[1];
    const float* W_ih   = (const float*)d_in[2];
    const float* W_hh   = (const float*)d_in[3];
    const float* b_ih   = (const float*)d_in[4];
    const float* b_hh   = (const float*)d_in[5];
    const float* W_enc  = (const float*)d_in[6];
    const float* W_dec  = (const float*)d_in[7];
    const float* b_attn = (const float*)d_in[8];
    const float* v_attn = (const float*)d_in[9];
    const float* W_out  = (const float*)d_in[10];
    const float* b_out  = (const float*)d_in[11];
    float* out = (float*)d_out;

    cudaFuncSetAttribute(decoder_kernel,
                         cudaFuncAttributeMaxDynamicSharedMemorySize, DSMEM_BYTES);

    prep_repack<<<256, 256>>>(W_ih, W_hh, W_out, W_dec);
    prep_encproj<<<BB * TE / 16, 256>>>(enc, W_enc);
    prep_transpose<<<dim3(TE / 32, ED / 32, BB), dim3(32, 8)>>>(enc);
    prep_gix<<<BB * TD / 8, 256>>>(gt, W_ih, b_ih, b_hh);
    decoder_kernel<<<BB * 4, 1024, DSMEM_BYTES>>>(b_attn, v_attn, b_hh, b_out, out);
}